// round 3
// baseline (speedup 1.0000x reference)
#include <cuda_runtime.h>
#include <math.h>

#define NN 40000
#define NE 640000
#define DD 64
#define KK2 25          // K*K = 25 spline kernels

// ---------------- scratch (device globals; no runtime allocation) -----------
__device__ float g_Y[(size_t)NN * KK2 * DD];   // 256 MB: Y[n][k][o]
__device__ float g_H[(size_t)NN * DD];         // layer-1 output
__device__ float g_AGG[(size_t)NN * DD];       // segment-max accumulator
__device__ int   g_SRC[NE];                    // normalized edge sources
__device__ int   g_DST[NE];                    // normalized edge dests

// ---------------- helpers ---------------------------------------------------
__device__ __forceinline__ void atomicMaxFloat(float* addr, float val) {
    // sign-split trick: valid for all finite floats with -inf init
    if (val >= 0.0f) atomicMax((int*)addr, __float_as_int(val));
    else             atomicMin((unsigned int*)addr, __float_as_uint(val));
}

// ---------------- 0) normalize edge_index (int32 OR int64, detected) --------
// If the buffer is int64 (little-endian, values < 40000), the odd 32-bit
// words of the first 8 entries are all zero. For int32 data that is ~impossible.
__global__ void convert_idx_kernel(const int* __restrict__ ei32) {
    // per-thread dtype detection from broadcast-cached words
    bool is64 = true;
    #pragma unroll
    for (int i = 0; i < 8; i++) is64 &= (__ldg(ei32 + 2 * i + 1) == 0);

    int e = blockIdx.x * blockDim.x + threadIdx.x;
    if (e >= NE) return;
    int s, d;
    if (is64) {
        s = __ldg(ei32 + 2 * e);            // low word of int64 src[e]
        d = __ldg(ei32 + 2 * (NE + e));     // low word of int64 dst[e]
    } else {
        s = __ldg(ei32 + e);
        d = __ldg(ei32 + NE + e);
    }
    g_SRC[e] = min(max(s, 0), NN - 1);      // defensive clamp (no-op normally)
    g_DST[e] = min(max(d, 0), NN - 1);
}

// ---------------- 1) init AGG to -inf ---------------------------------------
__global__ void init_agg_kernel() {
    int idx = blockIdx.x * blockDim.x + threadIdx.x;   // over float4s
    if (idx < NN * DD / 4) {
        ((float4*)g_AGG)[idx] =
            make_float4(-INFINITY, -INFINITY, -INFINITY, -INFINITY);
    }
}

// ---------------- 2) batched GEMM: Y[n][k][:] = X[n][:] @ W[k] ---------------
// grid = (ceil(NN/256), 25), block = 256 threads, per-thread 8x8 tile
#define TN 256
#define XPAD 68         // node stride 32 rows -> bank step 4 (conflict-free)
#define GEMM_SMEM ((TN * XPAD + DD * DD) * 4)

__global__ __launch_bounds__(256, 2) void gemm_kernel(const float* __restrict__ X,
                                                      const float* __restrict__ W) {
    extern __shared__ float sm[];
    float* xs = sm;               // [TN][XPAD]
    float* ws = sm + TN * XPAD;   // [64][64]  (W[k], i-major)

    const int k  = blockIdx.y;
    const int n0 = blockIdx.x * TN;
    const int t  = threadIdx.x;

    // W[k] tile (16 KB), coalesced float4
    const float4* Wk4 = (const float4*)(W + (size_t)k * DD * DD);
    #pragma unroll
    for (int idx = t; idx < DD * DD / 4; idx += 256)
        ((float4*)ws)[idx] = Wk4[idx];

    // X tile (256 x 64), coalesced float4, tail-guarded
    #pragma unroll
    for (int idx = t; idx < TN * (DD / 4); idx += 256) {
        int n  = idx / (DD / 4);
        int i4 = idx % (DD / 4);
        int gn = n0 + n;
        float4 v = (gn < NN) ? ((const float4*)(X + (size_t)gn * DD))[i4]
                             : make_float4(0.f, 0.f, 0.f, 0.f);
        *(float4*)(xs + n * XPAD + i4 * 4) = v;
    }
    __syncthreads();

    const int ox = (t & 7) * 8;   // 8 consecutive output cols
    const int ny = t >> 3;        // node group; rows ny + 32*r

    float acc[8][8];
    #pragma unroll
    for (int r = 0; r < 8; r++)
        #pragma unroll
        for (int c = 0; c < 8; c++) acc[r][c] = 0.0f;

    #pragma unroll 4
    for (int i = 0; i < DD; i++) {
        float4 b0 = *(const float4*)(ws + i * DD + ox);
        float4 b1 = *(const float4*)(ws + i * DD + ox + 4);
        float b[8] = {b0.x, b0.y, b0.z, b0.w, b1.x, b1.y, b1.z, b1.w};
        float a[8];
        #pragma unroll
        for (int r = 0; r < 8; r++) a[r] = xs[(ny + 32 * r) * XPAD + i];
        #pragma unroll
        for (int r = 0; r < 8; r++)
            #pragma unroll
            for (int c = 0; c < 8; c++) acc[r][c] = fmaf(a[r], b[c], acc[r][c]);
    }

    #pragma unroll
    for (int r = 0; r < 8; r++) {
        int gn = n0 + ny + 32 * r;
        if (gn < NN) {
            float* dst = g_Y + ((size_t)gn * KK2 + k) * DD + ox;
            *(float4*)(dst)     = make_float4(acc[r][0], acc[r][1], acc[r][2], acc[r][3]);
            *(float4*)(dst + 4) = make_float4(acc[r][4], acc[r][5], acc[r][6], acc[r][7]);
        }
    }
}

// ---------------- 3) edge kernel: basis + gather + weighted sum + atomicMax --
// One warp per edge. Kernel indices are always base + {0,1,5,6}: two
// contiguous 512B spans of Y[src] -> fully coalesced float2 loads per lane.
__global__ void edge_kernel(const float* __restrict__ attr) {
    int gt   = blockIdx.x * blockDim.x + threadIdx.x;
    int e    = gt >> 5;
    int lane = gt & 31;
    if (e >= NE) return;

    int src = g_SRC[e];
    int dst = g_DST[e];
    float a0 = __ldg(attr + 2 * e);
    float a1 = __ldg(attr + 2 * e + 1);

    // degree-1 open B-spline basis (K=5)
    float v0 = a0 * 4.0f, v1 = a1 * 4.0f;
    float b0f = fminf(fmaxf(floorf(v0), 0.0f), 3.0f);
    float b1f = fminf(fmaxf(floorf(v1), 0.0f), 3.0f);
    float f0 = v0 - b0f, f1 = v1 - b1f;
    int base = (int)b0f * 5 + (int)b1f;
    float g0 = 1.0f - f0, g1 = 1.0f - f1;
    float B0 = g0 * g1, B1 = g0 * f1, B2 = f0 * g1, B3 = f0 * f1;

    const float* yb = g_Y + ((size_t)src * KK2 + base) * DD;
    int d = lane * 2;
    float2 y0 = *(const float2*)(yb + d);             // kernel base
    float2 y1 = *(const float2*)(yb + DD + d);        // base+1
    float2 y2 = *(const float2*)(yb + 5 * DD + d);    // base+5
    float2 y3 = *(const float2*)(yb + 6 * DD + d);    // base+6

    float m0 = B0 * y0.x + B1 * y1.x + B2 * y2.x + B3 * y3.x;
    float m1 = B0 * y0.y + B1 * y1.y + B2 * y2.y + B3 * y3.y;

    float* ag = g_AGG + (size_t)dst * DD + d;
    atomicMaxFloat(ag,     m0);
    atomicMaxFloat(ag + 1, m1);
}

// ---------------- 4) finalize: out = fix(AGG) + X@root + bias (+relu) -------
__global__ void finalize_kernel(const float* __restrict__ X,
                                const float* __restrict__ root,
                                const float* __restrict__ bias,
                                float* __restrict__ out, int relu) {
    __shared__ float rs[DD * DD];    // root, i-major [i][o]
    __shared__ float xsh[16 * DD];   // 16 node rows
    int t  = threadIdx.x;
    int n0 = blockIdx.x * 16;

    #pragma unroll
    for (int idx = t; idx < DD * DD / 4; idx += 256)
        ((float4*)rs)[idx] = ((const float4*)root)[idx];
    #pragma unroll
    for (int idx = t; idx < 16 * DD / 4; idx += 256)
        ((float4*)xsh)[idx] = ((const float4*)(X + (size_t)n0 * DD))[idx];
    __syncthreads();

    int dcol = t & 63;
    int g    = t >> 6;   // 0..3 -> nodes g*4 .. g*4+3
    float acc[4] = {0.f, 0.f, 0.f, 0.f};
    #pragma unroll 4
    for (int i = 0; i < DD; i++) {
        float rv = rs[i * DD + dcol];
        #pragma unroll
        for (int r = 0; r < 4; r++)
            acc[r] = fmaf(xsh[(g * 4 + r) * DD + i], rv, acc[r]);
    }
    float bv = __ldg(bias + dcol);
    #pragma unroll
    for (int r = 0; r < 4; r++) {
        int n = n0 + g * 4 + r;
        float a = g_AGG[(size_t)n * DD + dcol];
        if (!isfinite(a)) a = 0.0f;           // nodes with no in-edges
        float val = a + acc[r] + bv;
        if (relu) val = fmaxf(val, 0.0f);
        out[(size_t)n * DD + dcol] = val;
    }
}

// ---------------- host launch ------------------------------------------------
extern "C" void kernel_launch(void* const* d_in, const int* in_sizes, int n_in,
                              void* d_out, int out_size) {
    const float* x     = (const float*)d_in[0];
    const int*   ei32  = (const int*)d_in[1];   // int32 OR int64 (device-detected)
    const float* attr  = (const float*)d_in[2];
    const float* W1    = (const float*)d_in[3];
    const float* root1 = (const float*)d_in[4];
    const float* bias1 = (const float*)d_in[5];
    const float* W2    = (const float*)d_in[6];
    const float* root2 = (const float*)d_in[7];
    const float* bias2 = (const float*)d_in[8];
    float*       out   = (float*)d_out;

    cudaFuncSetAttribute(gemm_kernel, cudaFuncAttributeMaxDynamicSharedMemorySize,
                         GEMM_SMEM);

    float* H = nullptr;
    cudaGetSymbolAddress((void**)&H, g_H);   // host-side query, not an allocation

    const int gemm_gx = (NN + TN - 1) / TN;          // 157
    dim3 gemm_grid(gemm_gx, KK2);
    const int edge_blocks = (NE * 32) / 256;         // 80000
    const int agg_blocks  = (NN * DD / 4) / 256;     // 2500
    const int fin_blocks  = NN / 16;                 // 2500
    const int cvt_blocks  = (NE + 255) / 256;        // 2500

    convert_idx_kernel<<<cvt_blocks, 256>>>(ei32);

    // ---- layer 1 ----
    init_agg_kernel<<<agg_blocks, 256>>>();
    gemm_kernel<<<gemm_grid, 256, GEMM_SMEM>>>(x, W1);
    edge_kernel<<<edge_blocks, 256>>>(attr);
    finalize_kernel<<<fin_blocks, 256>>>(x, root1, bias1, H, 1);

    // ---- layer 2 ----
    init_agg_kernel<<<agg_blocks, 256>>>();
    gemm_kernel<<<gemm_grid, 256, GEMM_SMEM>>>(H, W2);
    edge_kernel<<<edge_blocks, 256>>>(attr);
    finalize_kernel<<<fin_blocks, 256>>>(H, root2, bias2, out, 0);
}

// round 4
// speedup vs baseline: 1.1103x; 1.1103x over previous
#include <cuda_runtime.h>
#include <cuda_fp16.h>
#include <math.h>

#define NN 40000
#define NE 640000
#define DD 64
#define KK2 25          // K*K = 25 spline kernels

// ---------------- scratch (device globals; no runtime allocation) -----------
__device__ __half g_Yh[(size_t)NN * KK2 * DD];  // 128 MB: Y[n][k][o] in fp16
__device__ float  g_H[(size_t)NN * DD];         // layer-1 output
__device__ float  g_AGG[(size_t)NN * DD];       // segment-max accumulator
__device__ int    g_SRC[NE];                    // normalized edge sources
__device__ int    g_DST[NE];                    // normalized edge dests

// ---------------- helpers ---------------------------------------------------
__device__ __forceinline__ void atomicMaxFloat(float* addr, float val) {
    // sign-split trick: valid for all finite floats with -inf init
    if (val >= 0.0f) atomicMax((int*)addr, __float_as_int(val));
    else             atomicMin((unsigned int*)addr, __float_as_uint(val));
}

// ---------------- 0) normalize edge_index (int32 OR int64, detected) --------
__global__ void convert_idx_kernel(const int* __restrict__ ei32) {
    bool is64 = true;
    #pragma unroll
    for (int i = 0; i < 8; i++) is64 &= (__ldg(ei32 + 2 * i + 1) == 0);

    int e = blockIdx.x * blockDim.x + threadIdx.x;
    if (e >= NE) return;
    int s, d;
    if (is64) {
        s = __ldg(ei32 + 2 * e);
        d = __ldg(ei32 + 2 * (NE + e));
    } else {
        s = __ldg(ei32 + e);
        d = __ldg(ei32 + NE + e);
    }
    g_SRC[e] = min(max(s, 0), NN - 1);
    g_DST[e] = min(max(d, 0), NN - 1);
}

// ---------------- 1) init AGG to -inf ---------------------------------------
__global__ void init_agg_kernel() {
    int idx = blockIdx.x * blockDim.x + threadIdx.x;
    if (idx < NN * DD / 4) {
        ((float4*)g_AGG)[idx] =
            make_float4(-INFINITY, -INFINITY, -INFINITY, -INFINITY);
    }
}

// ---------------- 2) batched GEMM: Yh[n][k][:] = fp16(X[n][:] @ W[k]) --------
// grid = (ceil(NN/256), 25), block = 256, per-thread 8x8 tile over 8
// CONSECUTIVE rows (ny*8+r). XPAD=65 (odd): within a warp the 4 distinct
// row-bases differ by 8*65=520 words = 8 banks -> conflict-free a-loads.
#define TN 256
#define XPAD 65
#define GEMM_SMEM ((TN * XPAD + DD * DD) * 4)

__global__ __launch_bounds__(256, 2) void gemm_kernel(const float* __restrict__ X,
                                                      const float* __restrict__ W) {
    extern __shared__ float sm[];
    float* xs = sm;               // [TN][XPAD]
    float* ws = sm + TN * XPAD;   // [64][64]  (W[k], i-major)

    const int k  = blockIdx.y;
    const int n0 = blockIdx.x * TN;
    const int t  = threadIdx.x;

    // W[k] tile (16 KB), coalesced float4
    const float4* Wk4 = (const float4*)(W + (size_t)k * DD * DD);
    #pragma unroll
    for (int idx = t; idx < DD * DD / 4; idx += 256)
        ((float4*)ws)[idx] = Wk4[idx];

    // X tile (256 x 64): coalesced float4 gmem load, scalar smem stores
    // (row stride 65 floats is not 16B-aligned)
    #pragma unroll
    for (int idx = t; idx < TN * (DD / 4); idx += 256) {
        int n  = idx / (DD / 4);
        int i4 = idx % (DD / 4);
        int gn = n0 + n;
        float4 v = (gn < NN) ? ((const float4*)(X + (size_t)gn * DD))[i4]
                             : make_float4(0.f, 0.f, 0.f, 0.f);
        float* p = xs + n * XPAD + i4 * 4;
        p[0] = v.x; p[1] = v.y; p[2] = v.z; p[3] = v.w;
    }
    __syncthreads();

    const int ox = (t & 7) * 8;   // 8 consecutive output cols
    const int ny = t >> 3;        // row base: rows ny*8 .. ny*8+7

    float acc[8][8];
    #pragma unroll
    for (int r = 0; r < 8; r++)
        #pragma unroll
        for (int c = 0; c < 8; c++) acc[r][c] = 0.0f;

    #pragma unroll 4
    for (int i = 0; i < DD; i++) {
        float4 b0 = *(const float4*)(ws + i * DD + ox);
        float4 b1 = *(const float4*)(ws + i * DD + ox + 4);
        float b[8] = {b0.x, b0.y, b0.z, b0.w, b1.x, b1.y, b1.z, b1.w};
        float a[8];
        #pragma unroll
        for (int r = 0; r < 8; r++) a[r] = xs[(ny * 8 + r) * XPAD + i];
        #pragma unroll
        for (int r = 0; r < 8; r++)
            #pragma unroll
            for (int c = 0; c < 8; c++) acc[r][c] = fmaf(a[r], b[c], acc[r][c]);
    }

    #pragma unroll
    for (int r = 0; r < 8; r++) {
        int gn = n0 + ny * 8 + r;
        if (gn < NN) {
            __half2 h[4];
            #pragma unroll
            for (int c = 0; c < 4; c++)
                h[c] = __float22half2_rn(make_float2(acc[r][2*c], acc[r][2*c+1]));
            // 16B store of 8 halves; (gn*25+k)*64+ox is a multiple of 8 halves
            *(uint4*)(g_Yh + ((size_t)gn * KK2 + k) * DD + ox) =
                *(uint4*)h;
        }
    }
}

// ---------------- 3) edge kernel: basis + fp16 gather + atomicMax -----------
// One warp per edge; each row of Y is 128 B (64 halves) -> one half2 per lane.
__global__ void edge_kernel(const float* __restrict__ attr) {
    int gt   = blockIdx.x * blockDim.x + threadIdx.x;
    int e    = gt >> 5;
    int lane = gt & 31;
    if (e >= NE) return;

    int src = g_SRC[e];
    int dst = g_DST[e];
    float a0 = __ldg(attr + 2 * e);
    float a1 = __ldg(attr + 2 * e + 1);

    // degree-1 open B-spline basis (K=5)
    float v0 = a0 * 4.0f, v1 = a1 * 4.0f;
    float b0f = fminf(fmaxf(floorf(v0), 0.0f), 3.0f);
    float b1f = fminf(fmaxf(floorf(v1), 0.0f), 3.0f);
    float f0 = v0 - b0f, f1 = v1 - b1f;
    int base = (int)b0f * 5 + (int)b1f;
    float g0 = 1.0f - f0, g1 = 1.0f - f1;
    float B0 = g0 * g1, B1 = g0 * f1, B2 = f0 * g1, B3 = f0 * f1;

    const __half2* yb =
        (const __half2*)(g_Yh + ((size_t)src * KK2 + base) * DD);
    float2 y0 = __half22float2(__ldg(yb + lane));            // kernel base
    float2 y1 = __half22float2(__ldg(yb + 32 + lane));       // base+1
    float2 y2 = __half22float2(__ldg(yb + 5 * 32 + lane));   // base+5
    float2 y3 = __half22float2(__ldg(yb + 6 * 32 + lane));   // base+6

    float m0 = B0 * y0.x + B1 * y1.x + B2 * y2.x + B3 * y3.x;
    float m1 = B0 * y0.y + B1 * y1.y + B2 * y2.y + B3 * y3.y;

    float* ag = g_AGG + (size_t)dst * DD + lane * 2;
    atomicMaxFloat(ag,     m0);
    atomicMaxFloat(ag + 1, m1);
}

// ---------------- 4) finalize: out = fix(AGG) + X@root + bias (+relu) -------
__global__ void finalize_kernel(const float* __restrict__ X,
                                const float* __restrict__ root,
                                const float* __restrict__ bias,
                                float* __restrict__ out, int relu) {
    __shared__ float rs[DD * DD];    // root, i-major [i][o]
    __shared__ float xsh[16 * DD];   // 16 node rows
    int t  = threadIdx.x;
    int n0 = blockIdx.x * 16;

    #pragma unroll
    for (int idx = t; idx < DD * DD / 4; idx += 256)
        ((float4*)rs)[idx] = ((const float4*)root)[idx];
    #pragma unroll
    for (int idx = t; idx < 16 * DD / 4; idx += 256)
        ((float4*)xsh)[idx] = ((const float4*)(X + (size_t)n0 * DD))[idx];
    __syncthreads();

    int dcol = t & 63;
    int g    = t >> 6;   // 0..3 -> nodes g*4 .. g*4+3
    float acc[4] = {0.f, 0.f, 0.f, 0.f};
    #pragma unroll 4
    for (int i = 0; i < DD; i++) {
        float rv = rs[i * DD + dcol];
        #pragma unroll
        for (int r = 0; r < 4; r++)
            acc[r] = fmaf(xsh[(g * 4 + r) * DD + i], rv, acc[r]);
    }
    float bv = __ldg(bias + dcol);
    #pragma unroll
    for (int r = 0; r < 4; r++) {
        int n = n0 + g * 4 + r;
        float a = g_AGG[(size_t)n * DD + dcol];
        if (!isfinite(a)) a = 0.0f;           // nodes with no in-edges
        float val = a + acc[r] + bv;
        if (relu) val = fmaxf(val, 0.0f);
        out[(size_t)n * DD + dcol] = val;
    }
}

// ---------------- host launch ------------------------------------------------
extern "C" void kernel_launch(void* const* d_in, const int* in_sizes, int n_in,
                              void* d_out, int out_size) {
    const float* x     = (const float*)d_in[0];
    const int*   ei32  = (const int*)d_in[1];   // int32 OR int64 (device-detected)
    const float* attr  = (const float*)d_in[2];
    const float* W1    = (const float*)d_in[3];
    const float* root1 = (const float*)d_in[4];
    const float* bias1 = (const float*)d_in[5];
    const float* W2    = (const float*)d_in[6];
    const float* root2 = (const float*)d_in[7];
    const float* bias2 = (const float*)d_in[8];
    float*       out   = (float*)d_out;

    cudaFuncSetAttribute(gemm_kernel, cudaFuncAttributeMaxDynamicSharedMemorySize,
                         GEMM_SMEM);

    float* H = nullptr;
    cudaGetSymbolAddress((void**)&H, g_H);   // host-side query, not an allocation

    const int gemm_gx = (NN + TN - 1) / TN;          // 157
    dim3 gemm_grid(gemm_gx, KK2);
    const int edge_blocks = (NE * 32) / 256;         // 80000
    const int agg_blocks  = (NN * DD / 4) / 256;     // 2500
    const int fin_blocks  = NN / 16;                 // 2500
    const int cvt_blocks  = (NE + 255) / 256;        // 2500

    convert_idx_kernel<<<cvt_blocks, 256>>>(ei32);

    // ---- layer 1 ----
    init_agg_kernel<<<agg_blocks, 256>>>();
    gemm_kernel<<<gemm_grid, 256, GEMM_SMEM>>>(x, W1);
    edge_kernel<<<edge_blocks, 256>>>(attr);
    finalize_kernel<<<fin_blocks, 256>>>(x, root1, bias1, H, 1);

    // ---- layer 2 ----
    init_agg_kernel<<<agg_blocks, 256>>>();
    gemm_kernel<<<gemm_grid, 256, GEMM_SMEM>>>(H, W2);
    edge_kernel<<<edge_blocks, 256>>>(attr);
    finalize_kernel<<<fin_blocks, 256>>>(H, root2, bias2, out, 0);
}